// round 7
// baseline (speedup 1.0000x reference)
#include <cuda_runtime.h>
#include <cuda_fp16.h>
#include <cstdint>
#include <mma.h>

using namespace nvcuda;

#define EPSF 0.1f
constexpr int BB = 16, NN = 1024, DD = 2048;
constexpr int NITER_RUN = 14;      // contraction ~0.084/iter -> residual < 5e-5
#define LOGSCALE 6.2383246250395f  // ln(512)
#define LOG2E    1.44269504089f

// ---------------- static scratch (no allocations allowed) ----------------
__device__ __align__(128) signed char g_T8[(size_t)BB * NN * DD];     // int8-quantized teacher
__device__ __align__(128) signed char g_S8[(size_t)BB * NN * DD];     // int8-quantized student
__device__ float g_isT[BB * NN];                                      // per-row inv scale (teacher)
__device__ float g_isS[BB * NN];                                      // per-row inv scale (student)
__device__ __align__(128) unsigned char g_K [(size_t)BB * NN * NN];   // K_hat = 512*exp(-C/eps), e4m3
__device__ __align__(128) unsigned char g_KT[(size_t)BB * NN * NN];   // K_hat^T, e4m3
__device__ __align__(128) __half g_L [(size_t)BB * NN * NN];          // L = K_hat8 * C_tilde, fp16
__device__ float    g_phi[BB * NN];
__device__ float    g_gam[BB * NN];
__device__ unsigned g_bar[BB];
__device__ float    g_partial[128];

// ---------------- helpers ----------------
__device__ __forceinline__ __half2 fp8x2_to_half2(unsigned short v) {
    unsigned r;
    asm("cvt.rn.f16x2.e4m3x2 %0, %1;" : "=r"(r) : "h"(v));
    return *reinterpret_cast<__half2*>(&r);
}
__device__ __forceinline__ unsigned short floats_to_fp8x2(float lo, float hi) {
    unsigned short r;
    asm("cvt.rn.satfinite.e4m3x2.f32 %0, %1, %2;" : "=h"(r) : "f"(hi), "f"(lo));
    return r;
}
// FFMA-only exp2: floor split + endpoint-exact cubic (rel err ~1e-4). No MUFU.
__device__ __forceinline__ float fast_exp2(float y) {
    float fn = floorf(y);
    float f  = y - fn;
    float m  = fmaf(f, fmaf(f, fmaf(f, 0.0790209f, 0.2252015f), 0.6957776f), 1.0f);
    float sc = __int_as_float(((int)fn + 127) << 23);
    return m * sc;
}
__device__ __forceinline__ unsigned sptr32(const void* p) {
    return (unsigned)__cvta_generic_to_shared(p);
}
__device__ __forceinline__ void cp16(void* s, const void* g) {
    asm volatile("cp.async.cg.shared.global [%0], [%1], 16;\n" :: "r"(sptr32(s)), "l"(g));
}
__device__ __forceinline__ void cp_commit() { asm volatile("cp.async.commit_group;\n"); }
__device__ __forceinline__ void cp_wait1()  { asm volatile("cp.async.wait_group 1;\n"); }

// ---------------- normalization + int8 quantization (+ state init) ----------------
// q_i = round(127 * x_i / max|x_row|)  (norm-independent); invs = max|x|*rn/127
__global__ void __launch_bounds__(256) norm_kernel(const float* __restrict__ teacher,
                                                   const float* __restrict__ student) {
    if (blockIdx.x < 64) {
        int i = blockIdx.x * 256 + threadIdx.x;
        g_gam[i] = 1.0f;
        if (i < BB) g_bar[i] = 0u;
    }

    int row  = blockIdx.x * 8 + (threadIdx.x >> 5);
    int lane = threadIdx.x & 31;
    const float* x;
    signed char* o;
    float* isv;
    if (row < BB * NN) { x = teacher + (size_t)row * DD; o = g_T8 + (size_t)row * DD; isv = g_isT + row; }
    else { int r2 = row - BB*NN; x = student + (size_t)r2 * DD; o = g_S8 + (size_t)r2 * DD; isv = g_isS + r2; }

    const float4* p = (const float4*)x;
    float s = 0.f, mx = 0.f;
    #pragma unroll 4
    for (int t = lane; t < DD / 4; t += 32) {
        float4 q = p[t];
        s += q.x*q.x + q.y*q.y + q.z*q.z + q.w*q.w;
        mx = fmaxf(mx, fmaxf(fmaxf(fabsf(q.x), fabsf(q.y)), fmaxf(fabsf(q.z), fabsf(q.w))));
    }
    #pragma unroll
    for (int off = 16; off; off >>= 1) {
        s  += __shfl_xor_sync(0xffffffffu, s, off);
        mx  = fmaxf(mx, __shfl_xor_sync(0xffffffffu, mx, off));
    }
    float rn   = rsqrtf(fmaxf(s, 1e-24f));
    float qs   = 127.0f / fmaxf(mx, 1e-20f);     // quantize scale
    if (lane == 0) *isv = mx * rn * (1.0f / 127.0f);

    int* oi = (int*)o;
    for (int t = lane; t < DD / 4; t += 32) {
        float4 q = p[t];
        int a0 = __float2int_rn(q.x * qs), a1 = __float2int_rn(q.y * qs);
        int a2 = __float2int_rn(q.z * qs), a3 = __float2int_rn(q.w * qs);
        oi[t] = (a0 & 0xFF) | ((a1 & 0xFF) << 8) | ((a2 & 0xFF) << 16) | (a3 << 24);
    }
}

// ---------------- int8 wmma GEMM: dot = T8 * S8^T; epilogue K_hat fp8 (K,K^T), L fp16 ----------------
constexpr int GTILE = 128, GKT = 64, GPITCH = 80; // bytes (int8 elements)

__global__ void __launch_bounds__(256) gemm_kernel() {
    // mainloop: 2 stages * (128*80 A + 128*80 B) = 40960 B
    // epilogue: sO int 64*132*4 = 33792 | sK8 8448 @33792 | sIT 256 @42240 | sIS 512 @42496
    __shared__ __align__(16) char smem_raw[43008];
    const int b  = blockIdx.z;
    const int i0 = blockIdx.y * GTILE;
    const int j0 = blockIdx.x * GTILE;

    signed char* sA = (signed char*)smem_raw;                 // [2][128*80]
    signed char* sB = sA + 2 * GTILE * GPITCH;                // [2][128*80]

    const signed char* A  = g_T8 + (size_t)b * NN * DD + (size_t)i0 * DD;
    const signed char* Bm = g_S8 + (size_t)b * NN * DD + (size_t)j0 * DD;

    const int tid = threadIdx.x;
    const int wid = tid >> 5;
    const int wm  = wid & 3;   // 4 row-warps, 32 rows each
    const int wn  = wid >> 2;  // 2 col-warps, 64 cols each

    auto load_stage = [&](int stage, int kt) {
        int k0 = kt * GKT;
        #pragma unroll
        for (int x = tid; x < 512; x += 256) {
            int r = x >> 2, c = x & 3;
            cp16(&sA[stage*GTILE*GPITCH + r*GPITCH + c*16], A  + (size_t)r*DD + k0 + c*16);
            cp16(&sB[stage*GTILE*GPITCH + r*GPITCH + c*16], Bm + (size_t)r*DD + k0 + c*16);
        }
        cp_commit();
    };

    wmma::fragment<wmma::accumulator, 16, 16, 16, int> acc[2][4];
    #pragma unroll
    for (int r = 0; r < 2; r++)
        #pragma unroll
        for (int c = 0; c < 4; c++) wmma::fill_fragment(acc[r][c], 0);

    load_stage(0, 0);
    load_stage(1, 1);

    const int NK = DD / GKT; // 32
    for (int kt = 0; kt < NK; ++kt) {
        cp_wait1();
        __syncthreads();
        const int st = kt & 1;
        const signed char* a  = &sA[st * GTILE * GPITCH];
        const signed char* bp = &sB[st * GTILE * GPITCH];
        #pragma unroll
        for (int kk = 0; kk < GKT; kk += 16) {
            wmma::fragment<wmma::matrix_a, 16, 16, 16, signed char, wmma::row_major> af[2];
            wmma::fragment<wmma::matrix_b, 16, 16, 16, signed char, wmma::col_major> bf[4];
            wmma::load_matrix_sync(af[0], a + (wm*32      ) * GPITCH + kk, GPITCH);
            wmma::load_matrix_sync(af[1], a + (wm*32 + 16 ) * GPITCH + kk, GPITCH);
            #pragma unroll
            for (int c = 0; c < 4; c++)
                wmma::load_matrix_sync(bf[c], bp + (wn*64 + 16*c) * GPITCH + kk, GPITCH);
            #pragma unroll
            for (int r = 0; r < 2; r++)
                #pragma unroll
                for (int c = 0; c < 4; c++)
                    wmma::mma_sync(acc[r][c], af[r], bf[c], acc[r][c]);
        }
        __syncthreads();
        if (kt + 2 < NK) load_stage(kt & 1, kt + 2);
        else             cp_commit();
    }

    // ---------------- epilogue ----------------
    int*           sO  = (int*)smem_raw;                          // 64 x 132 ints
    unsigned char* sK8 = (unsigned char*)(smem_raw + 33792);      // 64 x 132 bytes
    float*         sIT = (float*)(smem_raw + 42240);              // 64
    float*         sIS = (float*)(smem_raw + 42496);              // 128
    unsigned char* Kp  = g_K  + (size_t)b * NN * NN;
    unsigned char* KTp = g_KT + (size_t)b * NN * NN;
    __half*        Lp  = g_L  + (size_t)b * NN * NN;

    const float Ac = 5.0f * LOG2E;
    const float Bc = (LOGSCALE - 5.0f) * LOG2E;

    __syncthreads();
    if (tid < 128) sIS[tid] = g_isS[b * NN + j0 + tid];

    #pragma unroll
    for (int h = 0; h < 2; ++h) {
        __syncthreads();
        if ((wm >> 1) == h) {
            int wmL = wm & 1;
            #pragma unroll
            for (int r = 0; r < 2; r++)
                #pragma unroll
                for (int c = 0; c < 4; c++)
                    wmma::store_matrix_sync(&sO[(wmL*32 + 16*r)*132 + wn*64 + 16*c],
                                            acc[r][c], 132, wmma::mem_row_major);
        }
        if (tid < 64) sIT[tid] = g_isT[b * NN + i0 + h*64 + tid];
        __syncthreads();
        // pass 1: exp once; write K fp8 + consistent L fp16; stage fp8 in smem
        for (int x = tid; x < 64 * 64; x += 256) {
            int i = x >> 6, jp = x & 63;
            float it = sIT[i];
            float cos0 = (float)sO[i*132 + 2*jp    ] * it * sIS[2*jp    ];
            float cos1 = (float)sO[i*132 + 2*jp + 1] * it * sIS[2*jp + 1];
            float y0 = fmaf(Ac, cos0, Bc), y1 = fmaf(Ac, cos1, Bc);
            float k0 = fast_exp2(y0),      k1 = fast_exp2(y1);
            unsigned short pk = floats_to_fp8x2(k0, k1);
            ((unsigned short*)Kp)[(((size_t)(i0 + h*64 + i) * NN + j0) >> 1) + jp] = pk;
            ((unsigned short*)sK8)[i*66 + jp] = pk;
            // consistency-corrected cost: C~ = C - eps*ln(1+r), r = (K8-K)/K
            float2 kf = __half22float2(fp8x2_to_half2(pk));
            float r0 = (kf.x - k0) * fast_exp2(-y0);
            float r1 = (kf.y - k1) * fast_exp2(-y1);
            float Ct0 = (0.5f - 0.5f*cos0) - EPSF * (r0 - 0.5f*r0*r0);
            float Ct1 = (0.5f - 0.5f*cos1) - EPSF * (r1 - 0.5f*r1*r1);
            ((__half2*)Lp)[(((size_t)(i0 + h*64 + i) * NN + j0) >> 1) + jp] =
                __floats2half2_rn(kf.x * Ct0, kf.y * Ct1);
        }
        __syncthreads();
        // pass 2: K^T from staged fp8 bytes
        for (int x = tid; x < 128 * 32; x += 256) {
            int j = x >> 5, ip = x & 31;
            unsigned b0 = sK8[(2*ip    )*132 + j];
            unsigned b1 = sK8[(2*ip + 1)*132 + j];
            ((unsigned short*)KTp)[(((size_t)(j0 + j) * NN + i0 + h*64) >> 1) + ip] =
                (unsigned short)(b0 | (b1 << 8));
        }
    }
}

// ---------------- persistent factored-Sinkhorn kernel (fp8 K, half2 FMA) ----------------
__device__ __forceinline__ unsigned ld_acq(unsigned* p) {
    unsigned v;
    asm volatile("ld.acquire.gpu.u32 %0, [%1];" : "=r"(v) : "l"(p) : "memory");
    return v;
}

__global__ void __launch_bounds__(512) sinkhorn_kernel() {
    const int blk = blockIdx.x, b = blk >> 3, c = blk & 7;   // 8 CTAs per batch
    const int tid = threadIdx.x, lane = tid & 31, wid = tid >> 5;  // 16 warps

    const unsigned char* __restrict__ Kb  = g_K  + (size_t)b * NN * NN;
    const unsigned char* __restrict__ KTb = g_KT + (size_t)b * NN * NN;
    const __half*        __restrict__ Lb  = g_L  + (size_t)b * NN * NN;
    float* phi = g_phi + b * NN;
    float* gam = g_gam + b * NN;

    unsigned tgt = 0;
    __half2 wh[16];  // fp8 matvec: wh[s*8+t] = (v[s*512+lane*16+2t], v[..+2t+1])

    auto load_w = [&](const float* v) {
        #pragma unroll
        for (int s = 0; s < 2; s++) {
            const float4* p = (const float4*)(v + s*512 + lane*16);
            #pragma unroll
            for (int t = 0; t < 4; t++) {
                float4 q = __ldcg(p + t);
                wh[s*8 + 2*t    ] = __floats2half2_rn(q.x, q.y);
                wh[s*8 + 2*t + 1] = __floats2half2_rn(q.z, q.w);
            }
        }
    };

    // 8 rows/warp in 2 groups of 4 -> 8 uint4 loads in flight per warp
    auto matvec = [&](const unsigned char* __restrict__ M, float* outv) {
        #pragma unroll 1
        for (int g = 0; g < 2; ++g) {
            int i = c * 128 + wid * 8 + g * 4;
            uint4 q[4][2];
            #pragma unroll
            for (int r = 0; r < 4; r++) {
                const uint4* rp = (const uint4*)(M + (size_t)(i + r) * NN);
                q[r][0] = __ldg(rp + lane);
                q[r][1] = __ldg(rp + 32 + lane);
            }
            float sums[4];
            #pragma unroll
            for (int r = 0; r < 4; r++) {
                float acc = 0.f;
                #pragma unroll
                for (int s = 0; s < 2; s++) {
                    __half2 a = __float2half2_rn(0.f);
                    const unsigned short* u = (const unsigned short*)&q[r][s];
                    #pragma unroll
                    for (int t = 0; t < 8; t++)
                        a = __hfma2(fp8x2_to_half2(u[t]), wh[s*8 + t], a);
                    float2 f = __half22float2(a);
                    acc += f.x + f.y;
                }
                sums[r] = acc;
            }
            #pragma unroll
            for (int r = 0; r < 4; r++)
                #pragma unroll
                for (int off = 16; off; off >>= 1)
                    sums[r] += __shfl_xor_sync(0xffffffffu, sums[r], off);
            if (!lane) {
                #pragma unroll
                for (int r = 0; r < 4; r++) outv[i + r] = 1.f / sums[r];
            }
        }
    };

    auto barrier = [&](unsigned t8) {
        __syncthreads();
        if (tid == 0) {
            __threadfence();
            atomicAdd(&g_bar[b], 1u);
            while (ld_acq(&g_bar[b]) < t8) { }
        }
        __syncthreads();
    };

    for (int it = 0; it < NITER_RUN; ++it) {
        load_w(gam);               // gamma~ (init ones)
        matvec(Kb, phi);           // phi~ = 1 / (K_hat gamma~)
        tgt += 8; barrier(tgt);
        load_w(phi);
        matvec(KTb, gam);          // gamma~ = 1 / (K_hat^T phi~)
        tgt += 8; barrier(tgt);
    }

    // loss: loss_b = (1/N) sum_i phi~_i * sum_j gamma~_j * L_ij   (consistent C~, no logs)
    float w32[32];
    {
        const float4* p = (const float4*)(gam + lane * 8);
        #pragma unroll
        for (int s = 0; s < 4; s++) {
            float4 q0 = __ldcg(p + s * 64);
            float4 q1 = __ldcg(p + s * 64 + 1);
            w32[s*8+0]=q0.x; w32[s*8+1]=q0.y; w32[s*8+2]=q0.z; w32[s*8+3]=q0.w;
            w32[s*8+4]=q1.x; w32[s*8+5]=q1.y; w32[s*8+6]=q1.z; w32[s*8+7]=q1.w;
        }
    }
    float accv = 0.f;
    #pragma unroll 1
    for (int rr = 0; rr < 8; ++rr) {
        int i = c * 128 + wid * 8 + rr;
        const uint4* rp = (const uint4*)(Lb + (size_t)i * NN);
        float sum = 0.f;
        #pragma unroll
        for (int s = 0; s < 4; s++) {
            uint4 q = __ldg(rp + s * 32 + lane);
            const __half2* h2 = (const __half2*)&q;
            #pragma unroll
            for (int p2 = 0; p2 < 4; p2++) {
                float2 f = __half22float2(h2[p2]);
                sum = fmaf(f.x, w32[s*8 + p2*2    ], sum);
                sum = fmaf(f.y, w32[s*8 + p2*2 + 1], sum);
            }
        }
        #pragma unroll
        for (int off = 16; off; off >>= 1) sum += __shfl_xor_sync(0xffffffffu, sum, off);
        if (!lane) accv += phi[i] * sum;
    }
    __shared__ float sred[16];
    if (!lane) sred[wid] = accv;
    __syncthreads();
    if (tid == 0) {
        float t = 0.f;
        #pragma unroll
        for (int k2 = 0; k2 < 16; k2++) t += sred[k2];
        g_partial[blk] = t;
    }
}

// ---------------- final reduction to scalar ----------------
__global__ void finish_kernel(float* out) {
    int t = threadIdx.x;                 // 128 threads
    float v = g_partial[t];
    #pragma unroll
    for (int off = 16; off; off >>= 1) v += __shfl_xor_sync(0xffffffffu, v, off);
    __shared__ float s[4];
    if ((t & 31) == 0) s[t >> 5] = v;
    __syncthreads();
    if (t == 0) out[0] = (s[0] + s[1] + s[2] + s[3]) * (1.0f / (BB * (float)NN));
}

// ---------------- launch ----------------
extern "C" void kernel_launch(void* const* d_in, const int* in_sizes, int n_in,
                              void* d_out, int out_size) {
    const float* student = (const float*)d_in[0];   // [16,1024,2048]
    const float* teacher = (const float*)d_in[1];   // [16,1024,2048]

    norm_kernel<<<4096, 256>>>(teacher, student);
    gemm_kernel<<<dim3(8, 8, BB), 256>>>();
    sinkhorn_kernel<<<128, 512>>>();
    finish_kernel<<<1, 128>>>((float*)d_out);
}

// round 8
// speedup vs baseline: 2.8922x; 2.8922x over previous
#include <cuda_runtime.h>
#include <cuda_fp16.h>
#include <cstdint>
#include <mma.h>

using namespace nvcuda;

#define EPSF 0.1f
constexpr int BB = 16, NN = 1024, DD = 2048;
constexpr int NITER_RUN = 7;       // contraction ~0.085/iter, d0 ~1e-2 -> residual ~3e-9
#define LOGSCALE 6.2383246250395f  // ln(512)
#define LOG2E    1.44269504089f

// ---------------- static scratch (no allocations allowed) ----------------
__device__ __align__(128) __half g_Tn[(size_t)BB * NN * DD];          // normalized teacher fp16
__device__ __align__(128) __half g_Sn[(size_t)BB * NN * DD];          // normalized student fp16
__device__ __align__(128) unsigned char g_K [(size_t)BB * NN * NN];   // K_hat = 512*exp(-C/eps), e4m3
__device__ __align__(128) unsigned char g_KT[(size_t)BB * NN * NN];   // K_hat^T, e4m3
__device__ __align__(128) __half g_L [(size_t)BB * NN * NN];          // L = K_hat8 * C_tilde, fp16
__device__ float    g_phi[BB * NN];
__device__ float    g_gam[BB * NN];
__device__ unsigned g_bar[BB];
__device__ float    g_partial[128];

// ---------------- fp8 / math helpers ----------------
__device__ __forceinline__ __half2 fp8x2_to_half2(unsigned short v) {
    unsigned r;
    asm("cvt.rn.f16x2.e4m3x2 %0, %1;" : "=r"(r) : "h"(v));
    return *reinterpret_cast<__half2*>(&r);
}
__device__ __forceinline__ unsigned short floats_to_fp8x2(float lo, float hi) {
    unsigned short r;
    asm("cvt.rn.satfinite.e4m3x2.f32 %0, %1, %2;" : "=h"(r) : "f"(hi), "f"(lo));
    return r;
}
// FFMA-only exp2: floor split + endpoint-exact cubic (rel err ~1e-4). No MUFU.
__device__ __forceinline__ float fast_exp2(float y) {
    float fn = floorf(y);
    float f  = y - fn;
    float m  = fmaf(f, fmaf(f, fmaf(f, 0.0790209f, 0.2252015f), 0.6957776f), 1.0f);
    float sc = __int_as_float(((int)fn + 127) << 23);
    return m * sc;
}
__device__ __forceinline__ unsigned sptr32(const void* p) {
    return (unsigned)__cvta_generic_to_shared(p);
}
__device__ __forceinline__ void cp16(void* s, const void* g) {
    asm volatile("cp.async.cg.shared.global [%0], [%1], 16;\n" :: "r"(sptr32(s)), "l"(g));
}
__device__ __forceinline__ void cp_commit() { asm volatile("cp.async.commit_group;\n"); }
__device__ __forceinline__ void cp_wait1()  { asm volatile("cp.async.wait_group 1;\n"); }

// ---------------- normalization (+ state init): fp32 rows -> unit-norm fp16 ----------------
__global__ void __launch_bounds__(256) norm_kernel(const float* __restrict__ teacher,
                                                   const float* __restrict__ student) {
    if (blockIdx.x < 64) {
        int i = blockIdx.x * 256 + threadIdx.x;
        g_gam[i] = 1.0f;
        if (i < BB) g_bar[i] = 0u;
    }

    int row  = blockIdx.x * 8 + (threadIdx.x >> 5);
    int lane = threadIdx.x & 31;
    const float* x;
    __half* o;
    if (row < BB * NN) { x = teacher + (size_t)row * DD;            o = g_Tn + (size_t)row * DD; }
    else               { x = student + (size_t)(row - BB*NN) * DD;  o = g_Sn + (size_t)(row - BB*NN) * DD; }

    const float4* p = (const float4*)x;
    float s = 0.f;
    #pragma unroll 4
    for (int t = lane; t < DD / 4; t += 32) {
        float4 q = p[t];
        s += q.x*q.x + q.y*q.y + q.z*q.z + q.w*q.w;
    }
    #pragma unroll
    for (int off = 16; off; off >>= 1) s += __shfl_xor_sync(0xffffffffu, s, off);
    float rn = 1.f / fmaxf(sqrtf(s), 1e-12f);

    __half2* oh = (__half2*)o;
    for (int t = lane; t < DD / 4; t += 32) {
        float4 q = p[t];
        oh[2*t]   = __floats2half2_rn(q.x*rn, q.y*rn);
        oh[2*t+1] = __floats2half2_rn(q.z*rn, q.w*rn);
    }
}

// ---------------- fp16 wmma GEMM: cos = Tn*Sn^T; epilogue fp8 K/K^T + consistent fp16 L ----------------
constexpr int GTILE = 128, GKT = 32, GPITCH = 40; // halves

__global__ void __launch_bounds__(256) gemm_kernel() {
    // mainloop: 2 stages * 2 mats * 128*40*2B = 40960; epilogue sO 33792 + sK8 8448 = 42240
    __shared__ __align__(16) char smem_raw[42240];
    const int b  = blockIdx.z;
    const int i0 = blockIdx.y * GTILE;
    const int j0 = blockIdx.x * GTILE;

    __half* sA = (__half*)smem_raw;                 // [2][128*40]
    __half* sB = sA + 2 * GTILE * GPITCH;           // [2][128*40]

    const __half* A  = g_Tn + (size_t)b * NN * DD + (size_t)i0 * DD;
    const __half* Bm = g_Sn + (size_t)b * NN * DD + (size_t)j0 * DD;

    const int tid = threadIdx.x;
    const int wid = tid >> 5;
    const int wm  = wid & 3;   // 4 row-warps, 32 rows each
    const int wn  = wid >> 2;  // 2 col-warps, 64 cols each

    auto load_stage = [&](int stage, int kt) {
        int k0 = kt * GKT;
        #pragma unroll
        for (int x = tid; x < 512; x += 256) {
            int r = x >> 2, c = x & 3;
            cp16(&sA[stage*GTILE*GPITCH + r*GPITCH + c*8], A  + (size_t)r*DD + k0 + c*8);
            cp16(&sB[stage*GTILE*GPITCH + r*GPITCH + c*8], Bm + (size_t)r*DD + k0 + c*8);
        }
        cp_commit();
    };

    wmma::fragment<wmma::accumulator, 16, 16, 16, float> acc[2][4];
    #pragma unroll
    for (int r = 0; r < 2; r++)
        #pragma unroll
        for (int c = 0; c < 4; c++) wmma::fill_fragment(acc[r][c], 0.0f);

    load_stage(0, 0);
    load_stage(1, 1);

    const int NK = DD / GKT; // 64
    for (int kt = 0; kt < NK; ++kt) {
        cp_wait1();
        __syncthreads();
        const int st = kt & 1;
        const __half* a  = &sA[st * GTILE * GPITCH];
        const __half* bp = &sB[st * GTILE * GPITCH];
        #pragma unroll
        for (int kk = 0; kk < GKT; kk += 16) {
            wmma::fragment<wmma::matrix_a, 16, 16, 16, __half, wmma::row_major> af[2];
            wmma::fragment<wmma::matrix_b, 16, 16, 16, __half, wmma::col_major> bf[4];
            wmma::load_matrix_sync(af[0], a + (wm*32      ) * GPITCH + kk, GPITCH);
            wmma::load_matrix_sync(af[1], a + (wm*32 + 16 ) * GPITCH + kk, GPITCH);
            #pragma unroll
            for (int c = 0; c < 4; c++)
                wmma::load_matrix_sync(bf[c], bp + (wn*64 + 16*c) * GPITCH + kk, GPITCH);
            #pragma unroll
            for (int r = 0; r < 2; r++)
                #pragma unroll
                for (int c = 0; c < 4; c++)
                    wmma::mma_sync(acc[r][c], af[r], bf[c], acc[r][c]);
        }
        __syncthreads();
        if (kt + 2 < NK) load_stage(kt & 1, kt + 2);
        else             cp_commit();
    }

    // ---------------- epilogue in two 64-row halves ----------------
    float*         sO  = (float*)smem_raw;                       // 64 x 132 floats
    unsigned char* sK8 = (unsigned char*)(smem_raw + 64*132*4);  // 64 x 132 bytes
    unsigned char* Kp  = g_K  + (size_t)b * NN * NN;
    unsigned char* KTp = g_KT + (size_t)b * NN * NN;
    __half*        Lp  = g_L  + (size_t)b * NN * NN;

    const float Ac = 5.0f * LOG2E;
    const float Bc = (LOGSCALE - 5.0f) * LOG2E;

    #pragma unroll
    for (int h = 0; h < 2; ++h) {
        __syncthreads();
        if ((wm >> 1) == h) {
            int wmL = wm & 1;
            #pragma unroll
            for (int r = 0; r < 2; r++)
                #pragma unroll
                for (int c = 0; c < 4; c++)
                    wmma::store_matrix_sync(&sO[(wmL*32 + 16*r)*132 + wn*64 + 16*c],
                                            acc[r][c], 132, wmma::mem_row_major);
        }
        __syncthreads();
        // pass 1: exp ONCE; write fp8 K + consistency-corrected fp16 L; stage fp8 in smem
        for (int x = tid; x < 64 * 64; x += 256) {
            int i = x >> 6, jp = x & 63;
            float cos0 = sO[i*132 + 2*jp    ];
            float cos1 = sO[i*132 + 2*jp + 1];
            float y0 = fmaf(Ac, cos0, Bc), y1 = fmaf(Ac, cos1, Bc);
            float k0 = fast_exp2(y0),      k1 = fast_exp2(y1);
            unsigned short pk = floats_to_fp8x2(k0, k1);
            ((unsigned short*)Kp)[(((size_t)(i0 + h*64 + i) * NN + j0) >> 1) + jp] = pk;
            ((unsigned short*)sK8)[i*66 + jp] = pk;
            // consistency-corrected cost: C~ = C - eps*ln(1+r), r = (K8-K)/K   (validated R7)
            float2 kf = __half22float2(fp8x2_to_half2(pk));
            float r0 = (kf.x - k0) * fast_exp2(-y0);
            float r1 = (kf.y - k1) * fast_exp2(-y1);
            float Ct0 = (0.5f - 0.5f*cos0) - EPSF * (r0 - 0.5f*r0*r0);
            float Ct1 = (0.5f - 0.5f*cos1) - EPSF * (r1 - 0.5f*r1*r1);
            ((__half2*)Lp)[(((size_t)(i0 + h*64 + i) * NN + j0) >> 1) + jp] =
                __floats2half2_rn(kf.x * Ct0, kf.y * Ct1);
        }
        __syncthreads();
        // pass 2: K^T from staged fp8 bytes
        for (int x = tid; x < 128 * 32; x += 256) {
            int j = x >> 5, ip = x & 31;
            unsigned b0 = sK8[(2*ip    )*132 + j];
            unsigned b1 = sK8[(2*ip + 1)*132 + j];
            ((unsigned short*)KTp)[(((size_t)(j0 + j) * NN + i0 + h*64) >> 1) + ip] =
                (unsigned short)(b0 | (b1 << 8));
        }
    }
}

// ---------------- persistent factored-Sinkhorn kernel (fp8 K, half2 FMA) ----------------
__device__ __forceinline__ unsigned ld_acq(unsigned* p) {
    unsigned v;
    asm volatile("ld.acquire.gpu.u32 %0, [%1];" : "=r"(v) : "l"(p) : "memory");
    return v;
}

__global__ void __launch_bounds__(512) sinkhorn_kernel() {
    const int blk = blockIdx.x, b = blk >> 3, c = blk & 7;   // 8 CTAs per batch
    const int tid = threadIdx.x, lane = tid & 31, wid = tid >> 5;  // 16 warps

    const unsigned char* __restrict__ Kb  = g_K  + (size_t)b * NN * NN;
    const unsigned char* __restrict__ KTb = g_KT + (size_t)b * NN * NN;
    const __half*        __restrict__ Lb  = g_L  + (size_t)b * NN * NN;
    float* phi = g_phi + b * NN;
    float* gam = g_gam + b * NN;

    unsigned tgt = 0;
    __half2 wh[16];  // fp8 matvec: wh[s*8+t] = (v[s*512+lane*16+2t], v[..+2t+1])

    auto load_w = [&](const float* v) {
        #pragma unroll
        for (int s = 0; s < 2; s++) {
            const float4* p = (const float4*)(v + s*512 + lane*16);
            #pragma unroll
            for (int t = 0; t < 4; t++) {
                float4 q = __ldcg(p + t);
                wh[s*8 + 2*t    ] = __floats2half2_rn(q.x, q.y);
                wh[s*8 + 2*t + 1] = __floats2half2_rn(q.z, q.w);
            }
        }
    };

    // 8 rows/warp in 2 groups of 4 -> 8 uint4 loads in flight per warp
    auto matvec = [&](const unsigned char* __restrict__ M, float* outv) {
        #pragma unroll 1
        for (int g = 0; g < 2; ++g) {
            int i = c * 128 + wid * 8 + g * 4;
            uint4 q[4][2];
            #pragma unroll
            for (int r = 0; r < 4; r++) {
                const uint4* rp = (const uint4*)(M + (size_t)(i + r) * NN);
                q[r][0] = __ldg(rp + lane);
                q[r][1] = __ldg(rp + 32 + lane);
            }
            float sums[4];
            #pragma unroll
            for (int r = 0; r < 4; r++) {
                float acc = 0.f;
                #pragma unroll
                for (int s = 0; s < 2; s++) {
                    __half2 a = __float2half2_rn(0.f);
                    const unsigned short* u = (const unsigned short*)&q[r][s];
                    #pragma unroll
                    for (int t = 0; t < 8; t++)
                        a = __hfma2(fp8x2_to_half2(u[t]), wh[s*8 + t], a);
                    float2 f = __half22float2(a);
                    acc += f.x + f.y;
                }
                sums[r] = acc;
            }
            #pragma unroll
            for (int r = 0; r < 4; r++)
                #pragma unroll
                for (int off = 16; off; off >>= 1)
                    sums[r] += __shfl_xor_sync(0xffffffffu, sums[r], off);
            if (!lane) {
                #pragma unroll
                for (int r = 0; r < 4; r++) outv[i + r] = 1.f / sums[r];
            }
        }
    };

    auto barrier = [&](unsigned t8) {
        __syncthreads();
        if (tid == 0) {
            __threadfence();
            atomicAdd(&g_bar[b], 1u);
            while (ld_acq(&g_bar[b]) < t8) { }
        }
        __syncthreads();
    };

    for (int it = 0; it < NITER_RUN; ++it) {
        load_w(gam);               // gamma~ (init ones)
        matvec(Kb, phi);           // phi~ = 1 / (K_hat gamma~)
        tgt += 8; barrier(tgt);
        load_w(phi);
        matvec(KTb, gam);          // gamma~ = 1 / (K_hat^T phi~)
        tgt += 8; barrier(tgt);
    }

    // loss: loss_b = (1/N) sum_i phi~_i * sum_j gamma~_j * L_ij
    float w32[32];
    {
        const float4* p = (const float4*)(gam + lane * 8);
        #pragma unroll
        for (int s = 0; s < 4; s++) {
            float4 q0 = __ldcg(p + s * 64);
            float4 q1 = __ldcg(p + s * 64 + 1);
            w32[s*8+0]=q0.x; w32[s*8+1]=q0.y; w32[s*8+2]=q0.z; w32[s*8+3]=q0.w;
            w32[s*8+4]=q1.x; w32[s*8+5]=q1.y; w32[s*8+6]=q1.z; w32[s*8+7]=q1.w;
        }
    }
    float accv = 0.f;
    #pragma unroll 1
    for (int rr = 0; rr < 8; ++rr) {
        int i = c * 128 + wid * 8 + rr;
        const uint4* rp = (const uint4*)(Lb + (size_t)i * NN);
        float sum = 0.f;
        #pragma unroll
        for (int s = 0; s < 4; s++) {
            uint4 q = __ldg(rp + s * 32 + lane);
            const __half2* h2 = (const __half2*)&q;
            #pragma unroll
            for (int p2 = 0; p2 < 4; p2++) {
                float2 f = __half22float2(h2[p2]);
                sum = fmaf(f.x, w32[s*8 + p2*2    ], sum);
                sum = fmaf(f.y, w32[s*8 + p2*2 + 1], sum);
            }
        }
        #pragma unroll
        for (int off = 16; off; off >>= 1) sum += __shfl_xor_sync(0xffffffffu, sum, off);
        if (!lane) accv += phi[i] * sum;
    }
    __shared__ float sred[16];
    if (!lane) sred[wid] = accv;
    __syncthreads();
    if (tid == 0) {
        float t = 0.f;
        #pragma unroll
        for (int k2 = 0; k2 < 16; k2++) t += sred[k2];
        g_partial[blk] = t;
    }
}

// ---------------- final reduction to scalar ----------------
__global__ void finish_kernel(float* out) {
    int t = threadIdx.x;                 // 128 threads
    float v = g_partial[t];
    #pragma unroll
    for (int off = 16; off; off >>= 1) v += __shfl_xor_sync(0xffffffffu, v, off);
    __shared__ float s[4];
    if ((t & 31) == 0) s[t >> 5] = v;
    __syncthreads();
    if (t == 0) out[0] = (s[0] + s[1] + s[2] + s[3]) * (1.0f / (BB * (float)NN));
}

// ---------------- launch ----------------
extern "C" void kernel_launch(void* const* d_in, const int* in_sizes, int n_in,
                              void* d_out, int out_size) {
    const float* student = (const float*)d_in[0];   // [16,1024,2048]
    const float* teacher = (const float*)d_in[1];   // [16,1024,2048]

    norm_kernel<<<4096, 256>>>(teacher, student);
    gemm_kernel<<<dim3(8, 8, BB), 256>>>();
    sinkhorn_kernel<<<128, 512>>>();
    finish_kernel<<<1, 128>>>((float*)d_out);
}

// round 9
// speedup vs baseline: 2.9220x; 1.0103x over previous
#include <cuda_runtime.h>
#include <cuda_fp16.h>
#include <cstdint>
#include <mma.h>

using namespace nvcuda;

#define EPSF 0.1f
constexpr int BB = 16, NN = 1024, DD = 2048;
constexpr int NITER_RUN = 5;       // truncation ~5e-5 (empirically anchored at 7<->14 delta 4e-6)
#define LOGSCALE 6.2383246250395f  // ln(512)
#define LOG2E    1.44269504089f

// ---------------- static scratch (no allocations allowed) ----------------
__device__ __align__(128) __half g_Tn[(size_t)BB * NN * DD];          // normalized teacher fp16
__device__ __align__(128) __half g_Sn[(size_t)BB * NN * DD];          // normalized student fp16
__device__ __align__(128) unsigned char g_K [(size_t)BB * NN * NN];   // K_hat = 512*exp(-C/eps), e4m3
__device__ __align__(128) unsigned char g_KT[(size_t)BB * NN * NN];   // K_hat^T, e4m3
__device__ __align__(128) __half g_L [(size_t)BB * NN * NN];          // L = K_hat8 * C_tilde, fp16
__device__ float    g_phi[BB * NN];
__device__ float    g_gam[BB * NN];
__device__ unsigned g_bar[BB];
__device__ float    g_partial[128];
__device__ unsigned g_done;

// ---------------- fp8 / math helpers ----------------
__device__ __forceinline__ __half2 fp8x2_to_half2(unsigned short v) {
    unsigned r;
    asm("cvt.rn.f16x2.e4m3x2 %0, %1;" : "=r"(r) : "h"(v));
    return *reinterpret_cast<__half2*>(&r);
}
__device__ __forceinline__ unsigned short floats_to_fp8x2(float lo, float hi) {
    unsigned short r;
    asm("cvt.rn.satfinite.e4m3x2.f32 %0, %1, %2;" : "=h"(r) : "f"(hi), "f"(lo));
    return r;
}
// FFMA-only exp2: floor split + endpoint-exact cubic (rel err ~1e-4). No MUFU.
__device__ __forceinline__ float fast_exp2(float y) {
    float fn = floorf(y);
    float f  = y - fn;
    float m  = fmaf(f, fmaf(f, fmaf(f, 0.0790209f, 0.2252015f), 0.6957776f), 1.0f);
    float sc = __int_as_float(((int)fn + 127) << 23);
    return m * sc;
}
__device__ __forceinline__ unsigned sptr32(const void* p) {
    return (unsigned)__cvta_generic_to_shared(p);
}
__device__ __forceinline__ void cp16(void* s, const void* g) {
    asm volatile("cp.async.cg.shared.global [%0], [%1], 16;\n" :: "r"(sptr32(s)), "l"(g));
}
__device__ __forceinline__ void cp_commit() { asm volatile("cp.async.commit_group;\n"); }
__device__ __forceinline__ void cp_wait1()  { asm volatile("cp.async.wait_group 1;\n"); }

// ---------------- normalization (+ state init), 4 batches per launch ----------------
__global__ void __launch_bounds__(256) norm_kernel(const float* __restrict__ teacher,
                                                   const float* __restrict__ student, int b0) {
    if (b0 == 0 && blockIdx.x < 64) {
        int i = blockIdx.x * 256 + threadIdx.x;
        g_gam[i] = 1.0f;
        if (i < BB) g_bar[i] = 0u;
        if (i == 0) g_done = 0u;
    }

    int idx  = blockIdx.x * 8 + (threadIdx.x >> 5);   // 0..8191 (4 batches x 2048 rows)
    int lane = threadIdx.x & 31;
    int batch = b0 + (idx >> 11);
    int r = idx & 2047;
    const float* x;
    __half* o;
    if (r < NN) { size_t gr = (size_t)batch * NN + r;        x = teacher + gr * DD; o = g_Tn + gr * DD; }
    else        { size_t gr = (size_t)batch * NN + (r - NN); x = student + gr * DD; o = g_Sn + gr * DD; }

    const float4* p = (const float4*)x;
    float s = 0.f;
    #pragma unroll 4
    for (int t = lane; t < DD / 4; t += 32) {
        float4 q = p[t];
        s += q.x*q.x + q.y*q.y + q.z*q.z + q.w*q.w;
    }
    #pragma unroll
    for (int off = 16; off; off >>= 1) s += __shfl_xor_sync(0xffffffffu, s, off);
    float rn = 1.f / fmaxf(sqrtf(s), 1e-12f);

    __half2* oh = (__half2*)o;
    for (int t = lane; t < DD / 4; t += 32) {
        float4 q = p[t];
        oh[2*t]   = __floats2half2_rn(q.x*rn, q.y*rn);
        oh[2*t+1] = __floats2half2_rn(q.z*rn, q.w*rn);
    }
}

// ---------------- fp16 wmma GEMM (K-slab 64): cos = Tn*Sn^T; fp8 K/K^T + consistent fp16 L ----------------
constexpr int GTILE = 128, GKT = 64, GPITCH = 72;       // halves
constexpr int GSMEM_BYTES = 2 * 2 * GTILE * GPITCH * 2; // 73728

__global__ void __launch_bounds__(256) gemm_kernel(int b0) {
    extern __shared__ __align__(16) char smem_raw[];
    const int b  = b0 + blockIdx.z;
    const int i0 = blockIdx.y * GTILE;
    const int j0 = blockIdx.x * GTILE;

    __half* sA = (__half*)smem_raw;                 // [2][128*72]
    __half* sB = sA + 2 * GTILE * GPITCH;           // [2][128*72]

    const __half* A  = g_Tn + (size_t)b * NN * DD + (size_t)i0 * DD;
    const __half* Bm = g_Sn + (size_t)b * NN * DD + (size_t)j0 * DD;

    const int tid = threadIdx.x;
    const int wid = tid >> 5;
    const int wm  = wid & 3;   // 4 row-warps, 32 rows each
    const int wn  = wid >> 2;  // 2 col-warps, 64 cols each

    auto load_stage = [&](int stage, int kt) {
        int k0 = kt * GKT;
        #pragma unroll
        for (int x = tid; x < 1024; x += 256) {     // 128 rows x 8 chunks of 16B, A and B
            int r = x >> 3, c = x & 7;
            cp16(&sA[stage*GTILE*GPITCH + r*GPITCH + c*8], A  + (size_t)r*DD + k0 + c*8);
            cp16(&sB[stage*GTILE*GPITCH + r*GPITCH + c*8], Bm + (size_t)r*DD + k0 + c*8);
        }
        cp_commit();
    };

    wmma::fragment<wmma::accumulator, 16, 16, 16, float> acc[2][4];
    #pragma unroll
    for (int r = 0; r < 2; r++)
        #pragma unroll
        for (int c = 0; c < 4; c++) wmma::fill_fragment(acc[r][c], 0.0f);

    load_stage(0, 0);
    load_stage(1, 1);

    const int NK = DD / GKT; // 32
    for (int kt = 0; kt < NK; ++kt) {
        cp_wait1();
        __syncthreads();
        const int st = kt & 1;
        const __half* a  = &sA[st * GTILE * GPITCH];
        const __half* bp = &sB[st * GTILE * GPITCH];
        #pragma unroll
        for (int kk = 0; kk < GKT; kk += 16) {
            wmma::fragment<wmma::matrix_a, 16, 16, 16, __half, wmma::row_major> af[2];
            wmma::fragment<wmma::matrix_b, 16, 16, 16, __half, wmma::col_major> bf[4];
            wmma::load_matrix_sync(af[0], a + (wm*32      ) * GPITCH + kk, GPITCH);
            wmma::load_matrix_sync(af[1], a + (wm*32 + 16 ) * GPITCH + kk, GPITCH);
            #pragma unroll
            for (int c = 0; c < 4; c++)
                wmma::load_matrix_sync(bf[c], bp + (wn*64 + 16*c) * GPITCH + kk, GPITCH);
            #pragma unroll
            for (int r = 0; r < 2; r++)
                #pragma unroll
                for (int c = 0; c < 4; c++)
                    wmma::mma_sync(acc[r][c], af[r], bf[c], acc[r][c]);
        }
        __syncthreads();
        if (kt + 2 < NK) load_stage(kt & 1, kt + 2);
        else             cp_commit();
    }

    // ---------------- epilogue in two 64-row halves ----------------
    float*         sO  = (float*)smem_raw;                       // 64 x 132 floats
    unsigned char* sK8 = (unsigned char*)(smem_raw + 64*132*4);  // 64 x 132 bytes
    unsigned char* Kp  = g_K  + (size_t)b * NN * NN;
    unsigned char* KTp = g_KT + (size_t)b * NN * NN;
    __half*        Lp  = g_L  + (size_t)b * NN * NN;

    const float Ac = 5.0f * LOG2E;
    const float Bc = (LOGSCALE - 5.0f) * LOG2E;

    #pragma unroll
    for (int h = 0; h < 2; ++h) {
        __syncthreads();
        if ((wm >> 1) == h) {
            int wmL = wm & 1;
            #pragma unroll
            for (int r = 0; r < 2; r++)
                #pragma unroll
                for (int c = 0; c < 4; c++)
                    wmma::store_matrix_sync(&sO[(wmL*32 + 16*r)*132 + wn*64 + 16*c],
                                            acc[r][c], 132, wmma::mem_row_major);
        }
        __syncthreads();
        // pass 1: exp ONCE; write fp8 K + consistency-corrected fp16 L; stage fp8 in smem
        for (int x = tid; x < 64 * 64; x += 256) {
            int i = x >> 6, jp = x & 63;
            float cos0 = sO[i*132 + 2*jp    ];
            float cos1 = sO[i*132 + 2*jp + 1];
            float y0 = fmaf(Ac, cos0, Bc), y1 = fmaf(Ac, cos1, Bc);
            float k0 = fast_exp2(y0),      k1 = fast_exp2(y1);
            unsigned short pk = floats_to_fp8x2(k0, k1);
            ((unsigned short*)Kp)[(((size_t)(i0 + h*64 + i) * NN + j0) >> 1) + jp] = pk;
            ((unsigned short*)sK8)[i*66 + jp] = pk;
            float2 kf = __half22float2(fp8x2_to_half2(pk));
            float r0 = (kf.x - k0) * fast_exp2(-y0);
            float r1 = (kf.y - k1) * fast_exp2(-y1);
            float Ct0 = (0.5f - 0.5f*cos0) - EPSF * (r0 - 0.5f*r0*r0);
            float Ct1 = (0.5f - 0.5f*cos1) - EPSF * (r1 - 0.5f*r1*r1);
            ((__half2*)Lp)[(((size_t)(i0 + h*64 + i) * NN + j0) >> 1) + jp] =
                __floats2half2_rn(kf.x * Ct0, kf.y * Ct1);
        }
        __syncthreads();
        // pass 2: K^T from staged fp8 bytes
        for (int x = tid; x < 128 * 32; x += 256) {
            int j = x >> 5, ip = x & 31;
            unsigned b0v = sK8[(2*ip    )*132 + j];
            unsigned b1v = sK8[(2*ip + 1)*132 + j];
            ((unsigned short*)KTp)[(((size_t)(j0 + j) * NN + i0 + h*64) >> 1) + ip] =
                (unsigned short)(b0v | (b1v << 8));
        }
    }
}

// ---------------- persistent factored-Sinkhorn kernel (fp8 K, half2 FMA) + fused finish ----------------
__device__ __forceinline__ unsigned ld_acq(unsigned* p) {
    unsigned v;
    asm volatile("ld.acquire.gpu.u32 %0, [%1];" : "=r"(v) : "l"(p) : "memory");
    return v;
}

__global__ void __launch_bounds__(512) sinkhorn_kernel(float* __restrict__ out) {
    const int blk = blockIdx.x, b = blk >> 3, c = blk & 7;   // 8 CTAs per batch
    const int tid = threadIdx.x, lane = tid & 31, wid = tid >> 5;  // 16 warps

    const unsigned char* __restrict__ Kb  = g_K  + (size_t)b * NN * NN;
    const unsigned char* __restrict__ KTb = g_KT + (size_t)b * NN * NN;
    const __half*        __restrict__ Lb  = g_L  + (size_t)b * NN * NN;
    float* phi = g_phi + b * NN;
    float* gam = g_gam + b * NN;

    unsigned tgt = 0;
    __half2 wh[16];  // wh[s*8+t] = (v[s*512+lane*16+2t], v[..+2t+1])

    auto load_w = [&](const float* v) {
        #pragma unroll
        for (int s = 0; s < 2; s++) {
            const float4* p = (const float4*)(v + s*512 + lane*16);
            #pragma unroll
            for (int t = 0; t < 4; t++) {
                float4 q = __ldcg(p + t);
                wh[s*8 + 2*t    ] = __floats2half2_rn(q.x, q.y);
                wh[s*8 + 2*t + 1] = __floats2half2_rn(q.z, q.w);
            }
        }
    };

    auto matvec = [&](const unsigned char* __restrict__ M, float* outv) {
        #pragma unroll 1
        for (int g = 0; g < 2; ++g) {
            int i = c * 128 + wid * 8 + g * 4;
            uint4 q[4][2];
            #pragma unroll
            for (int r = 0; r < 4; r++) {
                const uint4* rp = (const uint4*)(M + (size_t)(i + r) * NN);
                q[r][0] = __ldg(rp + lane);
                q[r][1] = __ldg(rp + 32 + lane);
            }
            float sums[4];
            #pragma unroll
            for (int r = 0; r < 4; r++) {
                float acc = 0.f;
                #pragma unroll
                for (int s = 0; s < 2; s++) {
                    __half2 a = __float2half2_rn(0.f);
                    const unsigned short* u = (const unsigned short*)&q[r][s];
                    #pragma unroll
                    for (int t = 0; t < 8; t++)
                        a = __hfma2(fp8x2_to_half2(u[t]), wh[s*8 + t], a);
                    float2 f = __half22float2(a);
                    acc += f.x + f.y;
                }
                sums[r] = acc;
            }
            #pragma unroll
            for (int r = 0; r < 4; r++)
                #pragma unroll
                for (int off = 16; off; off >>= 1)
                    sums[r] += __shfl_xor_sync(0xffffffffu, sums[r], off);
            if (!lane) {
                #pragma unroll
                for (int r = 0; r < 4; r++) outv[i + r] = 1.f / sums[r];
            }
        }
    };

    auto barrier = [&](unsigned t8) {
        __syncthreads();
        if (tid == 0) {
            __threadfence();
            atomicAdd(&g_bar[b], 1u);
            while (ld_acq(&g_bar[b]) < t8) { }
        }
        __syncthreads();
    };

    for (int it = 0; it < NITER_RUN; ++it) {
        load_w(gam);
        matvec(Kb, phi);           // phi~ = 1 / (K_hat gamma~)
        tgt += 8; barrier(tgt);
        load_w(phi);
        matvec(KTb, gam);          // gamma~ = 1 / (K_hat^T phi~)
        tgt += 8; barrier(tgt);
    }

    // loss: loss_b = (1/N) sum_i phi~_i * sum_j gamma~_j * L_ij
    float w32[32];
    {
        const float4* p = (const float4*)(gam + lane * 8);
        #pragma unroll
        for (int s = 0; s < 4; s++) {
            float4 q0 = __ldcg(p + s * 64);
            float4 q1 = __ldcg(p + s * 64 + 1);
            w32[s*8+0]=q0.x; w32[s*8+1]=q0.y; w32[s*8+2]=q0.z; w32[s*8+3]=q0.w;
            w32[s*8+4]=q1.x; w32[s*8+5]=q1.y; w32[s*8+6]=q1.z; w32[s*8+7]=q1.w;
        }
    }
    float accv = 0.f;
    #pragma unroll 1
    for (int rr = 0; rr < 8; ++rr) {
        int i = c * 128 + wid * 8 + rr;
        const uint4* rp = (const uint4*)(Lb + (size_t)i * NN);
        float sum = 0.f;
        #pragma unroll
        for (int s = 0; s < 4; s++) {
            uint4 q = __ldg(rp + s * 32 + lane);
            const __half2* h2 = (const __half2*)&q;
            #pragma unroll
            for (int p2 = 0; p2 < 4; p2++) {
                float2 f = __half22float2(h2[p2]);
                sum = fmaf(f.x, w32[s*8 + p2*2    ], sum);
                sum = fmaf(f.y, w32[s*8 + p2*2 + 1], sum);
            }
        }
        #pragma unroll
        for (int off = 16; off; off >>= 1) sum += __shfl_xor_sync(0xffffffffu, sum, off);
        if (!lane) accv += phi[i] * sum;
    }
    __shared__ float sred[16];
    __shared__ unsigned slast;
    __shared__ float s2[4];
    if (!lane) sred[wid] = accv;
    __syncthreads();
    if (tid == 0) {
        float t = 0.f;
        #pragma unroll
        for (int k2 = 0; k2 < 16; k2++) t += sred[k2];
        g_partial[blk] = t;
        __threadfence();
        slast = atomicAdd(&g_done, 1u);
    }
    __syncthreads();
    // last CTA reduces all partials and writes the scalar (fused finish)
    if (slast == 127) {
        if (tid < 128) {
            float v = g_partial[tid];
            #pragma unroll
            for (int off = 16; off; off >>= 1) v += __shfl_xor_sync(0xffffffffu, v, off);
            if (!lane) s2[tid >> 5] = v;
        }
        __syncthreads();
        if (tid == 0) out[0] = (s2[0] + s2[1] + s2[2] + s2[3]) * (1.0f / (BB * (float)NN));
    }
}

// ---------------- launch: norm chunks on a forked stream, gemm chunks gated by events ----------------
extern "C" void kernel_launch(void* const* d_in, const int* in_sizes, int n_in,
                              void* d_out, int out_size) {
    const float* student = (const float*)d_in[0];   // [16,1024,2048]
    const float* teacher = (const float*)d_in[1];   // [16,1024,2048]

    cudaFuncSetAttribute(gemm_kernel, cudaFuncAttributeMaxDynamicSharedMemorySize, GSMEM_BYTES);

    cudaStream_t s1;
    cudaStreamCreateWithFlags(&s1, cudaStreamNonBlocking);
    cudaEvent_t evS, evN[4];
    cudaEventCreateWithFlags(&evS, cudaEventDisableTiming);
    for (int c = 0; c < 4; c++) cudaEventCreateWithFlags(&evN[c], cudaEventDisableTiming);

    cudaEventRecord(evS, 0);
    cudaStreamWaitEvent(s1, evS, 0);
    for (int c = 0; c < 4; c++) {
        norm_kernel<<<1024, 256, 0, s1>>>(teacher, student, c * 4);
        cudaEventRecord(evN[c], s1);
    }
    for (int c = 0; c < 4; c++) {
        cudaStreamWaitEvent(0, evN[c], 0);
        gemm_kernel<<<dim3(8, 8, 4), 256, GSMEM_BYTES>>>(c * 4);
    }
    sinkhorn_kernel<<<128, 512>>>((float*)d_out);
}

// round 10
// speedup vs baseline: 3.1862x; 1.0904x over previous
#include <cuda_runtime.h>
#include <cuda_fp16.h>
#include <cstdint>
#include <mma.h>

using namespace nvcuda;

#define EPSF 0.1f
constexpr int BB = 16, NN = 1024, DD = 2048;
constexpr int NITER_RUN = 5;       // truncation ~5e-5 (validated: 5 vs 7 iters, rel_err delta ~3e-6)
#define LOGSCALE 6.2383246250395f  // ln(512)
#define LOG2E    1.44269504089f

// ---------------- static scratch (no allocations allowed) ----------------
__device__ __align__(128) __half g_Tn[(size_t)BB * NN * DD];          // normalized teacher fp16
__device__ __align__(128) __half g_Sn[(size_t)BB * NN * DD];          // normalized student fp16
__device__ __align__(128) unsigned char g_K [(size_t)BB * NN * NN];   // K_hat = 512*exp(-C/eps), e4m3
__device__ __align__(128) __half g_L [(size_t)BB * NN * NN];          // L = K_hat8 * C_tilde, fp16
__device__ float    g_acc[BB * NITER_RUN * NN];                       // per-iteration column accumulators
__device__ unsigned g_bar[BB];
__device__ float    g_partial[128];
__device__ unsigned g_done;

// ---------------- fp8 / math helpers ----------------
__device__ __forceinline__ __half2 fp8x2_to_half2(unsigned short v) {
    unsigned r;
    asm("cvt.rn.f16x2.e4m3x2 %0, %1;" : "=r"(r) : "h"(v));
    return *reinterpret_cast<__half2*>(&r);
}
__device__ __forceinline__ unsigned short floats_to_fp8x2(float lo, float hi) {
    unsigned short r;
    asm("cvt.rn.satfinite.e4m3x2.f32 %0, %1, %2;" : "=h"(r) : "f"(hi), "f"(lo));
    return r;
}
// FFMA-only exp2: floor split + endpoint-exact cubic (rel err ~1e-4). No MUFU.
__device__ __forceinline__ float fast_exp2(float y) {
    float fn = floorf(y);
    float f  = y - fn;
    float m  = fmaf(f, fmaf(f, fmaf(f, 0.0790209f, 0.2252015f), 0.6957776f), 1.0f);
    float sc = __int_as_float(((int)fn + 127) << 23);
    return m * sc;
}
__device__ __forceinline__ unsigned sptr32(const void* p) {
    return (unsigned)__cvta_generic_to_shared(p);
}
__device__ __forceinline__ void cp16(void* s, const void* g) {
    asm volatile("cp.async.cg.shared.global [%0], [%1], 16;\n" :: "r"(sptr32(s)), "l"(g));
}
__device__ __forceinline__ void cp_commit() { asm volatile("cp.async.commit_group;\n"); }
__device__ __forceinline__ void cp_wait1()  { asm volatile("cp.async.wait_group 1;\n"); }
__device__ __forceinline__ void cp_wait0()  { asm volatile("cp.async.wait_group 0;\n"); }
__device__ __forceinline__ unsigned ld_acq(unsigned* p) {
    unsigned v;
    asm volatile("ld.acquire.gpu.u32 %0, [%1];" : "=r"(v) : "l"(p) : "memory");
    return v;
}

// ---------------- normalization (+ state init), 4 batches per launch ----------------
__global__ void __launch_bounds__(256) norm_kernel(const float* __restrict__ teacher,
                                                   const float* __restrict__ student, int b0) {
    if (b0 == 0) {
        if (blockIdx.x < 80) {   // zero g_acc: 80 * 256 * 4 = 81920 floats
            float4 z = make_float4(0.f, 0.f, 0.f, 0.f);
            ((float4*)g_acc)[blockIdx.x * 256 + threadIdx.x] = z;
        }
        if (blockIdx.x == 80) {
            if (threadIdx.x < BB) g_bar[threadIdx.x] = 0u;
            if (threadIdx.x == 0) g_done = 0u;
        }
    }

    int idx  = blockIdx.x * 8 + (threadIdx.x >> 5);   // 0..8191 (4 batches x 2048 rows)
    int lane = threadIdx.x & 31;
    int batch = b0 + (idx >> 11);
    int r = idx & 2047;
    const float* x;
    __half* o;
    if (r < NN) { size_t gr = (size_t)batch * NN + r;        x = teacher + gr * DD; o = g_Tn + gr * DD; }
    else        { size_t gr = (size_t)batch * NN + (r - NN); x = student + gr * DD; o = g_Sn + gr * DD; }

    const float4* p = (const float4*)x;
    float s = 0.f;
    #pragma unroll 4
    for (int t = lane; t < DD / 4; t += 32) {
        float4 q = p[t];
        s += q.x*q.x + q.y*q.y + q.z*q.z + q.w*q.w;
    }
    #pragma unroll
    for (int off = 16; off; off >>= 1) s += __shfl_xor_sync(0xffffffffu, s, off);
    float rn = 1.f / fmaxf(sqrtf(s), 1e-12f);

    __half2* oh = (__half2*)o;
    for (int t = lane; t < DD / 4; t += 32) {
        float4 q = p[t];
        oh[2*t]   = __floats2half2_rn(q.x*rn, q.y*rn);
        oh[2*t+1] = __floats2half2_rn(q.z*rn, q.w*rn);
    }
}

// ---------------- fp16 wmma GEMM (K-slab 64): cos = Tn*Sn^T; fp8 K + consistent fp16 L ----------------
constexpr int GTILE = 128, GKT = 64, GPITCH = 72;       // halves
constexpr int GSMEM_BYTES = 2 * 2 * GTILE * GPITCH * 2; // 73728

__global__ void __launch_bounds__(256) gemm_kernel(int b0) {
    extern __shared__ __align__(16) char smem_raw[];
    const int b  = b0 + blockIdx.z;
    const int i0 = blockIdx.y * GTILE;
    const int j0 = blockIdx.x * GTILE;

    __half* sA = (__half*)smem_raw;                 // [2][128*72]
    __half* sB = sA + 2 * GTILE * GPITCH;           // [2][128*72]

    const __half* A  = g_Tn + (size_t)b * NN * DD + (size_t)i0 * DD;
    const __half* Bm = g_Sn + (size_t)b * NN * DD + (size_t)j0 * DD;

    const int tid = threadIdx.x;
    const int wid = tid >> 5;
    const int wm  = wid & 3;   // 4 row-warps, 32 rows each
    const int wn  = wid >> 2;  // 2 col-warps, 64 cols each

    auto load_stage = [&](int stage, int kt) {
        int k0 = kt * GKT;
        #pragma unroll
        for (int x = tid; x < 1024; x += 256) {
            int r = x >> 3, c = x & 7;
            cp16(&sA[stage*GTILE*GPITCH + r*GPITCH + c*8], A  + (size_t)r*DD + k0 + c*8);
            cp16(&sB[stage*GTILE*GPITCH + r*GPITCH + c*8], Bm + (size_t)r*DD + k0 + c*8);
        }
        cp_commit();
    };

    wmma::fragment<wmma::accumulator, 16, 16, 16, float> acc[2][4];
    #pragma unroll
    for (int r = 0; r < 2; r++)
        #pragma unroll
        for (int c = 0; c < 4; c++) wmma::fill_fragment(acc[r][c], 0.0f);

    load_stage(0, 0);
    load_stage(1, 1);

    const int NK = DD / GKT; // 32
    for (int kt = 0; kt < NK; ++kt) {
        cp_wait1();
        __syncthreads();
        const int st = kt & 1;
        const __half* a  = &sA[st * GTILE * GPITCH];
        const __half* bp = &sB[st * GTILE * GPITCH];
        #pragma unroll
        for (int kk = 0; kk < GKT; kk += 16) {
            wmma::fragment<wmma::matrix_a, 16, 16, 16, __half, wmma::row_major> af[2];
            wmma::fragment<wmma::matrix_b, 16, 16, 16, __half, wmma::col_major> bf[4];
            wmma::load_matrix_sync(af[0], a + (wm*32      ) * GPITCH + kk, GPITCH);
            wmma::load_matrix_sync(af[1], a + (wm*32 + 16 ) * GPITCH + kk, GPITCH);
            #pragma unroll
            for (int c = 0; c < 4; c++)
                wmma::load_matrix_sync(bf[c], bp + (wn*64 + 16*c) * GPITCH + kk, GPITCH);
            #pragma unroll
            for (int r = 0; r < 2; r++)
                #pragma unroll
                for (int c = 0; c < 4; c++)
                    wmma::mma_sync(acc[r][c], af[r], bf[c], acc[r][c]);
        }
        __syncthreads();
        if (kt + 2 < NK) load_stage(kt & 1, kt + 2);
        else             cp_commit();
    }

    // ---------------- epilogue (no K^T anymore) in two 64-row halves ----------------
    float*         sO  = (float*)smem_raw;                       // 64 x 132 floats
    unsigned char* Kp  = g_K  + (size_t)b * NN * NN;
    __half*        Lp  = g_L  + (size_t)b * NN * NN;

    const float Ac = 5.0f * LOG2E;
    const float Bc = (LOGSCALE - 5.0f) * LOG2E;

    #pragma unroll
    for (int h = 0; h < 2; ++h) {
        __syncthreads();
        if ((wm >> 1) == h) {
            int wmL = wm & 1;
            #pragma unroll
            for (int r = 0; r < 2; r++)
                #pragma unroll
                for (int c = 0; c < 4; c++)
                    wmma::store_matrix_sync(&sO[(wmL*32 + 16*r)*132 + wn*64 + 16*c],
                                            acc[r][c], 132, wmma::mem_row_major);
        }
        __syncthreads();
        for (int x = tid; x < 64 * 64; x += 256) {
            int i = x >> 6, jp = x & 63;
            float cos0 = sO[i*132 + 2*jp    ];
            float cos1 = sO[i*132 + 2*jp + 1];
            float y0 = fmaf(Ac, cos0, Bc), y1 = fmaf(Ac, cos1, Bc);
            float k0 = fast_exp2(y0),      k1 = fast_exp2(y1);
            unsigned short pk = floats_to_fp8x2(k0, k1);
            ((unsigned short*)Kp)[(((size_t)(i0 + h*64 + i) * NN + j0) >> 1) + jp] = pk;
            // consistency-corrected cost: C~ = C - eps*ln(1+r), r = (K8-K)/K   (validated R7/R8)
            float2 kf = __half22float2(fp8x2_to_half2(pk));
            float r0 = (kf.x - k0) * fast_exp2(-y0);
            float r1 = (kf.y - k1) * fast_exp2(-y1);
            float Ct0 = (0.5f - 0.5f*cos0) - EPSF * (r0 - 0.5f*r0*r0);
            float Ct1 = (0.5f - 0.5f*cos1) - EPSF * (r1 - 0.5f*r1*r1);
            ((__half2*)Lp)[(((size_t)(i0 + h*64 + i) * NN + j0) >> 1) + jp] =
                __floats2half2_rn(kf.x * Ct0, kf.y * Ct1);
        }
    }
}

// ---------------- smem-resident Sinkhorn: 8 CTAs/batch, each owns 128 rows of K ----------------
// smem: K block 128x1024 fp8 @0 | phi f32[128] @131072 | gamma h2[512] @131584
//       gamma f32[1024] @133632 | phi*512 h2[128] @137728  -> total 138240 B
constexpr int SK_SMEM = 138240;
#define PHI_SCALE 512.0f

__global__ void __launch_bounds__(512) sinkhorn_kernel(float* __restrict__ out) {
    extern __shared__ __align__(16) char sm[];
    unsigned char* sK    = (unsigned char*)sm;
    float*         sphi  = (float*)(sm + 131072);
    __half2*       sg2   = (__half2*)(sm + 131584);
    float*         sgf   = (float*)(sm + 133632);
    __half2*       sphih = (__half2*)(sm + 137728);

    const int blk = blockIdx.x, b = blk >> 3, c = blk & 7;   // 8 CTAs per batch
    const int tid = threadIdx.x, lane = tid & 31, wid = tid >> 5;  // 16 warps

    const unsigned char* __restrict__ Kb = g_K + (size_t)b * NN * NN + (size_t)c * 128 * NN;
    const __half*        __restrict__ Lb = g_L + (size_t)b * NN * NN + (size_t)c * 128 * NN;
    float* acc_base = g_acc + (size_t)b * NITER_RUN * NN;

    // one-time fill: 128KB of K into smem
    #pragma unroll
    for (int x = tid; x < 8192; x += 512)
        cp16(sK + x * 16, Kb + x * 16);
    cp_commit();
    cp_wait0();
    sg2[tid] = __float2half2_rn(1.0f);   // gamma = 1
    __syncthreads();

    for (int it = 0; it < NITER_RUN; ++it) {
        // ---- phi-pass: warp owns rows wid*8..+7; lane covers j = c8*128 + lane*4 (+0..3)
        __half2 gr[16];
        #pragma unroll
        for (int c8 = 0; c8 < 8; c8++) {
            int gi = c8*64 + lane*2;
            gr[2*c8]   = sg2[gi];
            gr[2*c8+1] = sg2[gi + 1];
        }
        #pragma unroll
        for (int r8 = 0; r8 < 8; r8++) {
            int i = wid*8 + r8;
            float facc = 0.f;
            #pragma unroll
            for (int c8 = 0; c8 < 8; c8++) {
                unsigned u = *(unsigned*)(sK + i*1024 + c8*128 + lane*4);
                __half2 h0 = fp8x2_to_half2((unsigned short)(u & 0xFFFFu));
                __half2 h1 = fp8x2_to_half2((unsigned short)(u >> 16));
                __half2 p  = __hfma2(h1, gr[2*c8+1], __hmul2(h0, gr[2*c8]));
                float2 f = __half22float2(p);
                facc += f.x + f.y;
            }
            #pragma unroll
            for (int off = 16; off; off >>= 1) facc += __shfl_xor_sync(0xffffffffu, facc, off);
            if (!lane) {
                sphi[i]  = 1.f / facc;
                sphih[i] = __float2half2_rn(PHI_SCALE / facc);   // scaled to stay normal in half
            }
        }
        __syncthreads();

        // ---- gamma partial pass: thread owns columns j0 = 2*tid, j0+1
        float* acc = acc_base + it * NN;
        {
            const int j0 = 2 * tid;
            float px = 0.f, py = 0.f;
            #pragma unroll 2
            for (int ib = 0; ib < 128; ib += 8) {
                __half2 h = __float2half2_rn(0.f);
                #pragma unroll
                for (int k = 0; k < 8; k++) {
                    int i = ib + k;
                    unsigned short u = *(unsigned short*)(sK + i*1024 + j0);
                    h = __hfma2(fp8x2_to_half2(u), sphih[i], h);
                }
                float2 f = __half22float2(h);
                px += f.x; py += f.y;
            }
            atomicAdd(acc + j0,     px * (1.0f / PHI_SCALE));
            atomicAdd(acc + j0 + 1, py * (1.0f / PHI_SCALE));
        }
        // ---- one global barrier per iteration (8 CTAs of this batch)
        __syncthreads();
        if (tid == 0) {
            __threadfence();
            atomicAdd(&g_bar[b], 1u);
            unsigned t8 = 8u * (unsigned)(it + 1);
            while (ld_acq(&g_bar[b]) < t8) { }
        }
        __syncthreads();
        // ---- gamma = 1/acc, locally
        {
            const int j0 = 2 * tid;
            float a0 = __ldcg(acc + j0), a1 = __ldcg(acc + j0 + 1);
            float gm0 = 1.f / a0, gm1 = 1.f / a1;
            sgf[j0] = gm0; sgf[j0 + 1] = gm1;
            sg2[tid] = __floats2half2_rn(gm0, gm1);
        }
        __syncthreads();
    }

    // ---- loss: (1/N) sum_i phi_i * sum_j gamma_j * L_ij over own rows
    float accv = 0.f;
    #pragma unroll 1
    for (int r8 = 0; r8 < 8; ++r8) {
        int i = wid*8 + r8;
        const uint4* rp = (const uint4*)(Lb + (size_t)i * NN);
        float sum = 0.f;
        #pragma unroll
        for (int c4 = 0; c4 < 4; c4++) {
            uint4 q = __ldg(rp + c4*32 + lane);        // 8 halves, j = c4*256 + lane*8
            int j = c4*256 + lane*8;
            const __half2* h2 = (const __half2*)&q;
            float4 wa = *(float4*)(sgf + j);
            float4 wb = *(float4*)(sgf + j + 4);
            float2 f;
            f = __half22float2(h2[0]); sum = fmaf(f.x, wa.x, fmaf(f.y, wa.y, sum));
            f = __half22float2(h2[1]); sum = fmaf(f.x, wa.z, fmaf(f.y, wa.w, sum));
            f = __half22float2(h2[2]); sum = fmaf(f.x, wb.x, fmaf(f.y, wb.y, sum));
            f = __half22float2(h2[3]); sum = fmaf(f.x, wb.z, fmaf(f.y, wb.w, sum));
        }
        #pragma unroll
        for (int off = 16; off; off >>= 1) sum += __shfl_xor_sync(0xffffffffu, sum, off);
        if (!lane) accv += sphi[i] * sum;
    }
    __shared__ float sred[16];
    __shared__ unsigned slast;
    __shared__ float s2[4];
    if (!lane) sred[wid] = accv;
    __syncthreads();
    if (tid == 0) {
        float t = 0.f;
        #pragma unroll
        for (int k2 = 0; k2 < 16; k2++) t += sred[k2];
        g_partial[blk] = t;
        __threadfence();
        slast = atomicAdd(&g_done, 1u);
    }
    __syncthreads();
    if (slast == 127) {   // fused finish: last CTA reduces all partials
        if (tid < 128) {
            float v = g_partial[tid];
            #pragma unroll
            for (int off = 16; off; off >>= 1) v += __shfl_xor_sync(0xffffffffu, v, off);
            if (!lane) s2[tid >> 5] = v;
        }
        __syncthreads();
        if (tid == 0) out[0] = (s2[0] + s2[1] + s2[2] + s2[3]) * (1.0f / (BB * (float)NN));
    }
}

// ---------------- launch: norm chunks on forked stream, gemm gated by events ----------------
extern "C" void kernel_launch(void* const* d_in, const int* in_sizes, int n_in,
                              void* d_out, int out_size) {
    const float* student = (const float*)d_in[0];   // [16,1024,2048]
    const float* teacher = (const float*)d_in[1];   // [16,1024,2048]

    cudaFuncSetAttribute(gemm_kernel,     cudaFuncAttributeMaxDynamicSharedMemorySize, GSMEM_BYTES);
    cudaFuncSetAttribute(sinkhorn_kernel, cudaFuncAttributeMaxDynamicSharedMemorySize, SK_SMEM);

    cudaStream_t s1;
    cudaStreamCreateWithFlags(&s1, cudaStreamNonBlocking);
    cudaEvent_t evS, evN[4];
    cudaEventCreateWithFlags(&evS, cudaEventDisableTiming);
    for (int c = 0; c < 4; c++) cudaEventCreateWithFlags(&evN[c], cudaEventDisableTiming);

    cudaEventRecord(evS, 0);
    cudaStreamWaitEvent(s1, evS, 0);
    for (int c = 0; c < 4; c++) {
        norm_kernel<<<1024, 256, 0, s1>>>(teacher, student, c * 4);
        cudaEventRecord(evN[c], s1);
    }
    for (int c = 0; c < 4; c++) {
        cudaStreamWaitEvent(0, evN[c], 0);
        gemm_kernel<<<dim3(8, 8, 4), 256, GSMEM_BYTES>>>(c * 4);
    }
    sinkhorn_kernel<<<128, 512, SK_SMEM>>>((float*)d_out);
}